// round 13
// baseline (speedup 1.0000x reference)
#include <cuda_runtime.h>
#include <math.h>
#include <stdint.h>

#define SS    1024
#define Hd    768
#define NHq   16
#define KVHn  8
#define Dd    64
#define HQn   (NHq*Dd)        // 1024
#define QKVN  (HQn + 2*KVHn*Dd) // 2048
#define En    64
#define Kk    8
#define FFn   3072
#define CAPn  256
#define F32EPS 1.1920929e-07f

// ---------------- scratch (device globals; no allocation) ----------------
__device__ float g_xnorm[SS*Hd];
__device__ float g_qkv[SS*QKVN];
__device__ float g_q[NHq*SS*Dd];
__device__ float g_k[KVHn*SS*Dd];
__device__ float g_vT[KVHn*Dd*SS];
__device__ float g_scores[(size_t)NHq*SS*SS];
__device__ float g_attn[SS*HQn];
__device__ float g_hidden[SS*Hd];
__device__ float g_x2[SS*Hd];
__device__ float g_act[SS*FFn];
__device__ float g_shared[SS*Hd];
__device__ float g_logits[SS*En];
__device__ int   g_topi[SS*Kk];
__device__ float g_topw[SS*Kk];
__device__ int   g_slot[SS*Kk];
__device__ int   g_etok[En*CAPn];
__device__ int   g_ne[En];
__device__ uint32_t g_Xe[(size_t)En*CAPn*Hd/2];      // bf16x2 packed
__device__ uint32_t g_acte[(size_t)En*CAPn*FFn/2];   // bf16x2 packed
__device__ float g_eout[(size_t)En*CAPn*Hd];

// ================= mma helpers (portable PTX, no 'a' features) =================
__device__ __forceinline__ uint32_t cvt_tf32(float f) {
    uint32_t u;
    asm("cvt.rna.tf32.f32 %0, %1;" : "=r"(u) : "f"(f));
    return u;
}

__device__ __forceinline__ void mma_tf32(float* c, const uint32_t* a, uint32_t b0, uint32_t b1) {
    asm volatile(
        "mma.sync.aligned.m16n8k8.row.col.f32.tf32.tf32.f32 "
        "{%0,%1,%2,%3}, {%4,%5,%6,%7}, {%8,%9}, {%0,%1,%2,%3};"
        : "+f"(c[0]), "+f"(c[1]), "+f"(c[2]), "+f"(c[3])
        : "r"(a[0]), "r"(a[1]), "r"(a[2]), "r"(a[3]), "r"(b0), "r"(b1));
}

__device__ __forceinline__ void mma_bf16(float* c, const uint32_t* a, uint32_t b0, uint32_t b1) {
    asm volatile(
        "mma.sync.aligned.m16n8k16.row.col.f32.bf16.bf16.f32 "
        "{%0,%1,%2,%3}, {%4,%5,%6,%7}, {%8,%9}, {%0,%1,%2,%3};"
        : "+f"(c[0]), "+f"(c[1]), "+f"(c[2]), "+f"(c[3])
        : "r"(a[0]), "r"(a[1]), "r"(a[2]), "r"(a[3]), "r"(b0), "r"(b1));
}

__device__ __forceinline__ uint32_t pack_bf16(float lo, float hi) {
    uint32_t r;
    asm("cvt.rn.bf16x2.f32 %0, %1, %2;" : "=r"(r) : "f"(hi), "f"(lo));
    return r;
}

__device__ __forceinline__ void ldsm_x4(uint32_t& d0, uint32_t& d1, uint32_t& d2, uint32_t& d3,
                                        uint32_t addr) {
    asm volatile("ldmatrix.sync.aligned.m8n8.x4.shared.b16 {%0,%1,%2,%3}, [%4];"
                 : "=r"(d0), "=r"(d1), "=r"(d2), "=r"(d3) : "r"(addr));
}

__device__ __forceinline__ void cp_async16(uint32_t dst, const void* src) {
    asm volatile("cp.async.cg.shared.global [%0], [%1], 16;" :: "r"(dst), "l"(src) : "memory");
}
#define CP_COMMIT() asm volatile("cp.async.commit_group;" ::: "memory")
#define CP_WAIT0()  asm volatile("cp.async.wait_group 0;" ::: "memory")

__device__ __forceinline__ float silu_f(float x) {
    return x / (1.f + expf(-x));
}

// ============ tf32 tensor-core NT GEMM: C[z][128m,128n] = alpha*A@B^T (+res) ============
__global__ void __launch_bounds__(256)
gemm_mma(const float* __restrict__ A, const float* __restrict__ B,
         float* __restrict__ C, const float* __restrict__ res,
         int Kd, int lda, int ldb, int ldc, float alpha,
         long long sA, int dA, long long sB, int dB, long long sC, int dC,
         const int* __restrict__ rowLim, int causal)
{
    int z = blockIdx.z;
    int row0 = blockIdx.y * 128, col0 = blockIdx.x * 128;
    if (rowLim && row0 >= rowLim[z]) return;
    if (causal && col0 > row0 + 127) return;
    A += (long long)(z / dA) * sA;
    B += (long long)(z / dB) * sB;
    C += (long long)(z / dC) * sC;

    __shared__ uint32_t As[128][36];
    __shared__ uint32_t Bs[128][36];

    int tid = threadIdx.x;
    int wid = tid >> 5, lane = tid & 31;
    int wm = wid & 3, wn = wid >> 2;
    int g = lane >> 2, t = lane & 3;

    int crow = tid >> 1;
    int ckb = (tid & 1) * 16;
    const float* Ag = A + (size_t)(row0 + crow) * lda + ckb;
    const float* Bg = B + (size_t)(col0 + crow) * ldb + ckb;

    float acc[2][8][4];
    #pragma unroll
    for (int mt = 0; mt < 2; mt++)
        #pragma unroll
        for (int nt = 0; nt < 8; nt++)
            #pragma unroll
            for (int i = 0; i < 4; i++) acc[mt][nt][i] = 0.f;

    const int NC = Kd / 32;
    float4 av[4], bv[4];

    #pragma unroll
    for (int i = 0; i < 4; i++) {
        av[i] = *(const float4*)(Ag + i*4);
        bv[i] = *(const float4*)(Bg + i*4);
    }

    for (int c = 0; ; ) {
        #pragma unroll
        for (int i = 0; i < 4; i++) {
            uint4 pa, pb;
            pa.x = cvt_tf32(av[i].x); pa.y = cvt_tf32(av[i].y);
            pa.z = cvt_tf32(av[i].z); pa.w = cvt_tf32(av[i].w);
            pb.x = cvt_tf32(bv[i].x); pb.y = cvt_tf32(bv[i].y);
            pb.z = cvt_tf32(bv[i].z); pb.w = cvt_tf32(bv[i].w);
            *(uint4*)&As[crow][ckb + i*4] = pa;
            *(uint4*)&Bs[crow][ckb + i*4] = pb;
        }
        __syncthreads();

        bool more = (c + 1 < NC);
        if (more) {
            size_t off = (size_t)(c + 1) * 32;
            #pragma unroll
            for (int i = 0; i < 4; i++) {
                av[i] = *(const float4*)(Ag + off + i*4);
                bv[i] = *(const float4*)(Bg + off + i*4);
            }
        }

        #pragma unroll
        for (int ks = 0; ks < 4; ks++) {
            int k8 = ks * 8;
            uint32_t a[2][4];
            #pragma unroll
            for (int mt = 0; mt < 2; mt++) {
                int m = wm*32 + mt*16;
                a[mt][0] = As[m + g    ][k8 + t    ];
                a[mt][1] = As[m + g + 8][k8 + t    ];
                a[mt][2] = As[m + g    ][k8 + t + 4];
                a[mt][3] = As[m + g + 8][k8 + t + 4];
            }
            #pragma unroll
            for (int nt = 0; nt < 8; nt++) {
                int n = wn*64 + nt*8;
                uint32_t b0 = Bs[n + g][k8 + t];
                uint32_t b1 = Bs[n + g][k8 + t + 4];
                #pragma unroll
                for (int mt = 0; mt < 2; mt++)
                    mma_tf32(acc[mt][nt], a[mt], b0, b1);
            }
        }

        c++;
        if (!more) break;
        __syncthreads();
    }

    #pragma unroll
    for (int mt = 0; mt < 2; mt++) {
        int r0 = row0 + wm*32 + mt*16 + g;
        #pragma unroll
        for (int nt = 0; nt < 8; nt++) {
            int cc = col0 + wn*64 + nt*8 + t*2;
            float2 v0, v1;
            v0.x = alpha * acc[mt][nt][0];
            v0.y = alpha * acc[mt][nt][1];
            v1.x = alpha * acc[mt][nt][2];
            v1.y = alpha * acc[mt][nt][3];
            if (res) {
                float2 r0v = *(const float2*)&res[(size_t)r0 * ldc + cc];
                float2 r1v = *(const float2*)&res[(size_t)(r0+8) * ldc + cc];
                v0.x += r0v.x; v0.y += r0v.y;
                v1.x += r1v.x; v1.y += r1v.y;
            }
            *(float2*)&C[(size_t)r0 * ldc + cc] = v0;
            *(float2*)&C[(size_t)(r0+8) * ldc + cc] = v1;
        }
    }
}

// ============ tf32 fused gu GEMM + SwiGLU (shared MLP): Out[128m, 64ac] ============
__global__ void __launch_bounds__(256)
gemm_guact_tf32(const float* __restrict__ A, const float* __restrict__ B,
                float* __restrict__ Out,
                int Kd, int lda, int ldb, int ldout, int ffrows)
{
    int row0 = blockIdx.y * 128;
    int colact0 = blockIdx.x * 64;

    __shared__ uint32_t As[128][36];
    __shared__ uint32_t Bs[128][36];

    int tid = threadIdx.x;
    int wid = tid >> 5, lane = tid & 31;
    int wm = wid & 3, wn = wid >> 2;
    int g = lane >> 2, t = lane & 3;

    int crow = tid >> 1;
    int ckb = (tid & 1) * 16;
    const float* Ag = A + (size_t)(row0 + crow) * lda + ckb;
    int blk = crow >> 6, h = (crow >> 5) & 1, inner = crow & 31;
    int brow = h * ffrows + colact0 + blk * 32 + inner;
    const float* Bg = B + (size_t)brow * ldb + ckb;

    float acc[2][8][4];
    #pragma unroll
    for (int mt = 0; mt < 2; mt++)
        #pragma unroll
        for (int nt = 0; nt < 8; nt++)
            #pragma unroll
            for (int i = 0; i < 4; i++) acc[mt][nt][i] = 0.f;

    const int NC = Kd / 32;
    float4 av[4], bv[4];
    #pragma unroll
    for (int i = 0; i < 4; i++) {
        av[i] = *(const float4*)(Ag + i*4);
        bv[i] = *(const float4*)(Bg + i*4);
    }

    for (int c = 0; ; ) {
        #pragma unroll
        for (int i = 0; i < 4; i++) {
            uint4 pa, pb;
            pa.x = cvt_tf32(av[i].x); pa.y = cvt_tf32(av[i].y);
            pa.z = cvt_tf32(av[i].z); pa.w = cvt_tf32(av[i].w);
            pb.x = cvt_tf32(bv[i].x); pb.y = cvt_tf32(bv[i].y);
            pb.z = cvt_tf32(bv[i].z); pb.w = cvt_tf32(bv[i].w);
            *(uint4*)&As[crow][ckb + i*4] = pa;
            *(uint4*)&Bs[crow][ckb + i*4] = pb;
        }
        __syncthreads();

        bool more = (c + 1 < NC);
        if (more) {
            size_t off = (size_t)(c + 1) * 32;
            #pragma unroll
            for (int i = 0; i < 4; i++) {
                av[i] = *(const float4*)(Ag + off + i*4);
                bv[i] = *(const float4*)(Bg + off + i*4);
            }
        }

        #pragma unroll
        for (int ks = 0; ks < 4; ks++) {
            int k8 = ks * 8;
            uint32_t a[2][4];
            #pragma unroll
            for (int mt = 0; mt < 2; mt++) {
                int m = wm*32 + mt*16;
                a[mt][0] = As[m + g    ][k8 + t    ];
                a[mt][1] = As[m + g + 8][k8 + t    ];
                a[mt][2] = As[m + g    ][k8 + t + 4];
                a[mt][3] = As[m + g + 8][k8 + t + 4];
            }
            #pragma unroll
            for (int nt = 0; nt < 8; nt++) {
                int n = wn*64 + nt*8;
                uint32_t b0 = Bs[n + g][k8 + t];
                uint32_t b1 = Bs[n + g][k8 + t + 4];
                #pragma unroll
                for (int mt = 0; mt < 2; mt++)
                    mma_tf32(acc[mt][nt], a[mt], b0, b1);
            }
        }

        c++;
        if (!more) break;
        __syncthreads();
    }

    #pragma unroll
    for (int mt = 0; mt < 2; mt++) {
        int r0 = row0 + wm*32 + mt*16 + g;
        #pragma unroll
        for (int j = 0; j < 4; j++) {
            int ac = colact0 + wn*32 + j*8 + t*2;
            float2 v0, v1;
            v0.x = acc[mt][j][0] * silu_f(acc[mt][j+4][0]);
            v0.y = acc[mt][j][1] * silu_f(acc[mt][j+4][1]);
            v1.x = acc[mt][j][2] * silu_f(acc[mt][j+4][2]);
            v1.y = acc[mt][j][3] * silu_f(acc[mt][j+4][3]);
            *(float2*)&Out[(size_t)r0 * ldout + ac] = v0;
            *(float2*)&Out[(size_t)(r0+8) * ldout + ac] = v1;
        }
    }
}

// ============ tf32 PV GEMM: C[z][128m, 64n] = A[z]@B[z/2]^T, causal K-truncated ============
__global__ void __launch_bounds__(256)
gemm_pv(const float* __restrict__ A, const float* __restrict__ B,
        float* __restrict__ C, int Kd, int lda, int ldb, int ldc,
        long long sA, long long sB, long long sC)
{
    int z = blockIdx.z;
    int row0 = blockIdx.y * 128;
    A += (long long)z * sA;
    B += (long long)(z >> 1) * sB;
    C += (long long)z * sC;

    __shared__ uint32_t As[128][36];
    __shared__ uint32_t Bs[64][36];

    int tid = threadIdx.x;
    int wid = tid >> 5, lane = tid & 31;
    int wm = wid & 3, wn = wid >> 2;
    int g = lane >> 2, t = lane & 3;

    int crow = tid >> 1;
    int ckb = (tid & 1) * 16;
    const float* Ag = A + (size_t)(row0 + crow) * lda + ckb;
    const float* Bg = B + (size_t)(tid >> 2) * ldb + (tid & 3) * 8;

    float acc[2][4][4];
    #pragma unroll
    for (int mt = 0; mt < 2; mt++)
        #pragma unroll
        for (int nt = 0; nt < 4; nt++)
            #pragma unroll
            for (int i = 0; i < 4; i++) acc[mt][nt][i] = 0.f;

    int KdEff = row0 + 128;
    if (KdEff > Kd) KdEff = Kd;
    const int NC = KdEff / 32;

    float4 av[4], bv[2];
    #pragma unroll
    for (int i = 0; i < 4; i++) av[i] = *(const float4*)(Ag + i*4);
    #pragma unroll
    for (int i = 0; i < 2; i++) bv[i] = *(const float4*)(Bg + i*4);

    for (int c = 0; ; ) {
        #pragma unroll
        for (int i = 0; i < 4; i++) {
            uint4 pa;
            pa.x = cvt_tf32(av[i].x); pa.y = cvt_tf32(av[i].y);
            pa.z = cvt_tf32(av[i].z); pa.w = cvt_tf32(av[i].w);
            *(uint4*)&As[crow][ckb + i*4] = pa;
        }
        #pragma unroll
        for (int i = 0; i < 2; i++) {
            uint4 pb;
            pb.x = cvt_tf32(bv[i].x); pb.y = cvt_tf32(bv[i].y);
            pb.z = cvt_tf32(bv[i].z); pb.w = cvt_tf32(bv[i].w);
            *(uint4*)&Bs[tid >> 2][(tid & 3) * 8 + i*4] = pb;
        }
        __syncthreads();

        bool more = (c + 1 < NC);
        if (more) {
            size_t off = (size_t)(c + 1) * 32;
            #pragma unroll
            for (int i = 0; i < 4; i++) av[i] = *(const float4*)(Ag + off + i*4);
            #pragma unroll
            for (int i = 0; i < 2; i++) bv[i] = *(const float4*)(Bg + off + i*4);
        }

        #pragma unroll
        for (int ks = 0; ks < 4; ks++) {
            int k8 = ks * 8;
            uint32_t a[2][4];
            #pragma unroll
            for (int mt = 0; mt < 2; mt++) {
                int m = wm*32 + mt*16;
                a[mt][0] = As[m + g    ][k8 + t    ];
                a[mt][1] = As[m + g + 8][k8 + t    ];
                a[mt][2] = As[m + g    ][k8 + t + 4];
                a[mt][3] = As[m + g + 8][k8 + t + 4];
            }
            #pragma unroll
            for (int nt = 0; nt < 4; nt++) {
                int n = wn*32 + nt*8;
                uint32_t b0 = Bs[n + g][k8 + t];
                uint32_t b1 = Bs[n + g][k8 + t + 4];
                #pragma unroll
                for (int mt = 0; mt < 2; mt++)
                    mma_tf32(acc[mt][nt], a[mt], b0, b1);
            }
        }

        c++;
        if (!more) break;
        __syncthreads();
    }

    #pragma unroll
    for (int mt = 0; mt < 2; mt++) {
        int r0 = row0 + wm*32 + mt*16 + g;
        #pragma unroll
        for (int nt = 0; nt < 4; nt++) {
            int cc = wn*32 + nt*8 + t*2;
            float2 v0, v1;
            v0.x = acc[mt][nt][0]; v0.y = acc[mt][nt][1];
            v1.x = acc[mt][nt][2]; v1.y = acc[mt][nt][3];
            *(float2*)&C[(size_t)r0 * ldc + cc] = v0;
            *(float2*)&C[(size_t)(r0+8) * ldc + cc] = v1;
        }
    }
}

// ============ bf16 fused expert gu GEMM + SwiGLU; A packed bf16 via cp.async ============
__global__ void __launch_bounds__(256, 2)
gemm_guact_bf16(const uint32_t* __restrict__ A, const float* __restrict__ B,
                uint32_t* __restrict__ Out,
                int Kd, int ldau2, int ldb, int ldout2, int ffrows,
                long long sA2, long long sB, long long sOut2,
                const int* __restrict__ rowLim)
{
    int z = blockIdx.z;
    int row0 = blockIdx.y * 128;
    if (rowLim && row0 >= rowLim[z]) return;
    int colact0 = blockIdx.x * 64;
    A   += (long long)z * sA2;
    B   += (long long)z * sB;
    Out += (long long)z * sOut2;

    __shared__ uint32_t Asu[2][128][20];
    __shared__ uint32_t Bsu[2][128][20];

    int tid = threadIdx.x;
    int wid = tid >> 5, lane = tid & 31;
    int wm = wid & 3, wn = wid >> 2;
    int g = lane >> 2, t = lane & 3;
    int mi = lane >> 3, r = lane & 7;

    int crow = tid >> 1;
    int kh = tid & 1;
    const uint32_t* Ag = A + (size_t)(row0 + crow) * ldau2 + kh * 8;
    int blk = crow >> 6, h = (crow >> 5) & 1, inner = crow & 31;
    int brow = h * ffrows + colact0 + blk * 32 + inner;
    const float* Bg = B + (size_t)brow * ldb + kh * 16;

    uint32_t aDst[2];
    aDst[0] = (uint32_t)__cvta_generic_to_shared(&Asu[0][crow][kh*8]);
    aDst[1] = (uint32_t)__cvta_generic_to_shared(&Asu[1][crow][kh*8]);

    uint32_t aAddr[2][2], bAddr[2][4];
    #pragma unroll
    for (int buf = 0; buf < 2; buf++) {
        #pragma unroll
        for (int mt = 0; mt < 2; mt++) {
            int rowA = wm*32 + mt*16 + (mi & 1)*8 + r;
            aAddr[buf][mt] = (uint32_t)__cvta_generic_to_shared(&Asu[buf][rowA][(mi >> 1)*4]);
        }
        #pragma unroll
        for (int ntp = 0; ntp < 4; ntp++) {
            int rowB = wn*64 + ntp*16 + (mi >> 1)*8 + r;
            bAddr[buf][ntp] = (uint32_t)__cvta_generic_to_shared(&Bsu[buf][rowB][(mi & 1)*4]);
        }
    }

    float acc[2][8][4];
    #pragma unroll
    for (int mt = 0; mt < 2; mt++)
        #pragma unroll
        for (int j = 0; j < 8; j++)
            #pragma unroll
            for (int i = 0; i < 4; i++) acc[mt][j][i] = 0.f;

    const int NC = Kd / 32;
    float4 bv[4];

    cp_async16(aDst[0], Ag);
    cp_async16(aDst[0] + 16, Ag + 4);
    CP_COMMIT();
    #pragma unroll
    for (int i = 0; i < 4; i++) bv[i] = *(const float4*)(Bg + i*4);
    {
        int wb = kh * 8;
        #pragma unroll
        for (int i = 0; i < 4; i++) {
            uint2 pb;
            pb.x = pack_bf16(bv[i].x, bv[i].y); pb.y = pack_bf16(bv[i].z, bv[i].w);
            *(uint2*)&Bsu[0][crow][wb + i*2] = pb;
        }
    }
    CP_WAIT0();
    __syncthreads();

    for (int c = 0; c < NC; c++) {
        int buf = c & 1;
        bool more = (c + 1 < NC);
        if (more) {
            int nb = buf ^ 1;
            const uint32_t* Agc = Ag + (size_t)(c + 1) * 16;
            cp_async16(aDst[nb], Agc);
            cp_async16(aDst[nb] + 16, Agc + 4);
            CP_COMMIT();
            size_t offB = (size_t)(c + 1) * 32;
            #pragma unroll
            for (int i = 0; i < 4; i++) bv[i] = *(const float4*)(Bg + offB + i*4);
        }
        #pragma unroll
        for (int ks = 0; ks < 2; ks++) {
            uint32_t afr[2][4];
            #pragma unroll
            for (int mt = 0; mt < 2; mt++)
                ldsm_x4(afr[mt][0], afr[mt][1], afr[mt][2], afr[mt][3],
                        aAddr[buf][mt] + ks*32);
            #pragma unroll
            for (int ntp = 0; ntp < 4; ntp++) {
                uint32_t b00, b01, b10, b11;
                ldsm_x4(b00, b01, b10, b11, bAddr[buf][ntp] + ks*32);
                #pragma unroll
                for (int mt = 0; mt < 2; mt++) {
                    mma_bf16(acc[mt][2*ntp  ], afr[mt], b00, b01);
                    mma_bf16(acc[mt][2*ntp+1], afr[mt], b10, b11);
                }
            }
        }
        if (more) {
            int nb = buf ^ 1;
            int wb = kh * 8;
            #pragma unroll
            for (int i = 0; i < 4; i++) {
                uint2 pb;
                pb.x = pack_bf16(bv[i].x, bv[i].y); pb.y = pack_bf16(bv[i].z, bv[i].w);
                *(uint2*)&Bsu[nb][crow][wb + i*2] = pb;
            }
            CP_WAIT0();
            __syncthreads();
        }
    }

    #pragma unroll
    for (int mt = 0; mt < 2; mt++) {
        int r0 = row0 + wm*32 + mt*16 + g;
        #pragma unroll
        for (int j = 0; j < 4; j++) {
            int ac = colact0 + wn*32 + j*8 + t*2;
            float v0x = acc[mt][j][0] * silu_f(acc[mt][j+4][0]);
            float v0y = acc[mt][j][1] * silu_f(acc[mt][j+4][1]);
            float v1x = acc[mt][j][2] * silu_f(acc[mt][j+4][2]);
            float v1y = acc[mt][j][3] * silu_f(acc[mt][j+4][3]);
            Out[(size_t)r0 * ldout2 + (ac >> 1)] = pack_bf16(v0x, v0y);
            Out[(size_t)(r0+8) * ldout2 + (ac >> 1)] = pack_bf16(v1x, v1y);
        }
    }
}

// ============ bf16 NT GEMM, A packed bf16 via cp.async: C[z][128m,128n] = A@B^T ============
__global__ void __launch_bounds__(256, 2)
gemm_bf16_abf(const uint32_t* __restrict__ A, const float* __restrict__ B,
              float* __restrict__ C,
              int Kd, int ldau2, int ldb, int ldc,
              long long sA2, long long sB, long long sC,
              const int* __restrict__ rowLim)
{
    int z = blockIdx.z;
    int row0 = blockIdx.y * 128, col0 = blockIdx.x * 128;
    if (rowLim && row0 >= rowLim[z]) return;
    A += (long long)z * sA2;
    B += (long long)z * sB;
    C += (long long)z * sC;

    __shared__ uint32_t Asu[2][128][20];
    __shared__ uint32_t Bsu[2][128][20];

    int tid = threadIdx.x;
    int wid = tid >> 5, lane = tid & 31;
    int wm = wid & 3, wn = wid >> 2;
    int g = lane >> 2, t = lane & 3;
    int mi = lane >> 3, r = lane & 7;

    int crow = tid >> 1;
    int kh = tid & 1;
    const uint32_t* Ag = A + (size_t)(row0 + crow) * ldau2 + kh * 8;
    const float* Bg = B + (size_t)(col0 + crow) * ldb + kh * 16;

    uint32_t aDst[2];
    aDst[0] = (uint32_t)__cvta_generic_to_shared(&Asu[0][crow][kh*8]);
    aDst[1] = (uint32_t)__cvta_generic_to_shared(&Asu[1][crow][kh*8]);

    uint32_t aAddr[2][2], bAddr[2][4];
    #pragma unroll
    for (int buf = 0; buf < 2; buf++) {
        #pragma unroll
        for (int mt = 0; mt < 2; mt++) {
            int rowA = wm*32 + mt*16 + (mi & 1)*8 + r;
            aAddr[buf][mt] = (uint32_t)__cvta_generic_to_shared(&Asu[buf][rowA][(mi >> 1)*4]);
        }
        #pragma unroll
        for (int ntp = 0; ntp < 4; ntp++) {
            int rowB = wn*64 + ntp*16 + (mi >> 1)*8 + r;
            bAddr[buf][ntp] = (uint32_t)__cvta_generic_to_shared(&Bsu[buf][rowB][(mi & 1)*4]);
        }
    }

    float acc[2][8][4];
    #pragma unroll
    for (int mt = 0; mt < 2; mt++)
        #pragma unroll
        for (int j = 0; j < 8; j++)
            #pragma unroll
            for (int i = 0; i < 4; i++) acc[mt][j][i] = 0.f;

    const int NC = Kd / 32;
    float4 bv[4];

    cp_async16(aDst[0], Ag);
    cp_async16(aDst[0] + 16, Ag + 4);
    CP_COMMIT();
    #pragma unroll
    for (int i = 0; i < 4; i++) bv[i] = *(const float4*)(Bg + i*4);
    {
        int wb = kh * 8;
        #pragma unroll
        for (int i = 0; i < 4; i++) {
            uint2 pb;
            pb.x = pack_bf16(bv[i].x, bv[i].y); pb.y = pack_bf16(bv[i].z, bv[i].w);
            *(uint2*)&Bsu[0][crow][wb + i*2] = pb;
        }
    }
    CP_WAIT0();
    __syncthreads();

    for (int c = 0; c < NC; c++) {
        int buf = c & 1;
        bool more = (c + 1 < NC);
        if (more) {
            int nb = buf ^ 1;
            const uint32_t* Agc = Ag + (size_t)(c + 1) * 16;
            cp_async16(aDst[nb], Agc);
            cp_async16(aDst[nb] + 16, Agc + 4);
            CP_COMMIT();
            size_t offB = (size_t)(c + 1) * 32;
            #pragma unroll
            for (int i = 0; i < 4; i++) bv[i] = *(const float4*)(Bg + offB + i*4);
        }
        #pragma unroll
        for (int ks = 0; ks < 2; ks++) {
            uint32_t afr[2][4];
            #pragma unroll
            for (int mt = 0; mt < 2; mt++)
                ldsm_x4(afr[mt][0], afr[mt][1], afr[mt][2], afr[mt][3],
                        aAddr[buf][mt] + ks*32);
            #pragma unroll
            for (int ntp = 0; ntp < 4; ntp++) {
                uint32_t b00, b01, b10, b11;
                ldsm_x4(b00, b01, b10, b11, bAddr[buf][ntp] + ks*32);
                #pragma unroll
                for (int mt = 0; mt < 2; mt++) {
                    mma_bf16(acc[mt][2*ntp  ], afr[mt], b00, b01);
                    mma_bf16(acc[mt][2*ntp+1], afr[mt], b10, b11);
                }
            }
        }
        if (more) {
            int nb = buf ^ 1;
            int wb = kh * 8;
            #pragma unroll
            for (int i = 0; i < 4; i++) {
                uint2 pb;
                pb.x = pack_bf16(bv[i].x, bv[i].y); pb.y = pack_bf16(bv[i].z, bv[i].w);
                *(uint2*)&Bsu[nb][crow][wb + i*2] = pb;
            }
            CP_WAIT0();
            __syncthreads();
        }
    }

    #pragma unroll
    for (int mt = 0; mt < 2; mt++) {
        int r0 = row0 + wm*32 + mt*16 + g;
        #pragma unroll
        for (int j = 0; j < 8; j++) {
            int cc = col0 + wn*64 + j*8 + t*2;
            float2 v0, v1;
            v0.x = acc[mt][j][0]; v0.y = acc[mt][j][1];
            v1.x = acc[mt][j][2]; v1.y = acc[mt][j][3];
            *(float2*)&C[(size_t)r0 * ldc + cc] = v0;
            *(float2*)&C[(size_t)(r0+8) * ldc + cc] = v1;
        }
    }
}

// ================= generic 64x64 fp32 NT GEMM (router logits) =================
__global__ void gemm_nt(const float* __restrict__ A, const float* __restrict__ B,
                        float* __restrict__ C, const float* __restrict__ res,
                        int M, int N, int Kd, int lda, int ldb, int ldc, float alpha,
                        long long sA, int dA, long long sB, int dB, long long sC, int dC,
                        const int* __restrict__ rowLim, int causal)
{
    int z = blockIdx.z;
    int row0 = blockIdx.y * 64, col0 = blockIdx.x * 64;
    if (rowLim && row0 >= rowLim[z]) return;
    if (causal && col0 > row0 + 63) return;
    A += (long long)(z / dA) * sA;
    B += (long long)(z / dB) * sB;
    C += (long long)(z / dC) * sC;

    __shared__ float As[16][64];
    __shared__ float Bs[16][64];
    int tid = threadIdx.x;
    int tr = tid >> 2;
    int tk = (tid & 3) * 4;
    int ty = tid >> 4, tx = tid & 15;

    float c[4][4] = {};
    for (int k0 = 0; k0 < Kd; k0 += 16) {
        float4 a4 = *(const float4*)&A[(size_t)(row0 + tr) * lda + k0 + tk];
        float4 b4 = *(const float4*)&B[(size_t)(col0 + tr) * ldb + k0 + tk];
        As[tk+0][tr] = a4.x; As[tk+1][tr] = a4.y; As[tk+2][tr] = a4.z; As[tk+3][tr] = a4.w;
        Bs[tk+0][tr] = b4.x; Bs[tk+1][tr] = b4.y; Bs[tk+2][tr] = b4.z; Bs[tk+3][tr] = b4.w;
        __syncthreads();
        #pragma unroll
        for (int k = 0; k < 16; k++) {
            float a[4], b[4];
            #pragma unroll
            for (int i = 0; i < 4; i++) a[i] = As[k][ty*4 + i];
            #pragma unroll
            for (int j = 0; j < 4; j++) b[j] = Bs[k][tx*4 + j];
            #pragma unroll
            for (int i = 0; i < 4; i++)
                #pragma unroll
                for (int j = 0; j < 4; j++)
                    c[i][j] += a[i] * b[j];
        }
        __syncthreads();
    }
    #pragma unroll
    for (int i = 0; i < 4; i++) {
        int r = row0 + ty*4 + i;
        #pragma unroll
        for (int j = 0; j < 4; j++) {
            int cc = col0 + tx*4 + j;
            float v = alpha * c[i][j];
            if (res) v += res[(size_t)r * ldc + cc];
            C[(size_t)r * ldc + cc] = v;
        }
    }
}

// ---------------- RMSNorm over H=768 ----------------
__global__ void rmsnorm_k(const float* __restrict__ x, const float* __restrict__ w,
                          float* __restrict__ out)
{
    int s = blockIdx.x;
    const float* row = x + (size_t)s * Hd;
    __shared__ float red[256];
    float acc = 0.f;
    for (int i = threadIdx.x; i < Hd; i += 256) { float v = row[i]; acc += v * v; }
    red[threadIdx.x] = acc; __syncthreads();
    for (int o = 128; o > 0; o >>= 1) { if (threadIdx.x < o) red[threadIdx.x] += red[threadIdx.x + o]; __syncthreads(); }
    float inv = rsqrtf(red[0] / Hd + 1e-6f);
    for (int i = threadIdx.x; i < Hd; i += 256) out[(size_t)s * Hd + i] = w[i] * row[i] * inv;
}

// ---------------- split qkv + RoPE + per-head RMSNorm + v transpose ----------------
__global__ void rope_split_k(const float* __restrict__ cosb, const float* __restrict__ sinb,
                             const float* __restrict__ qw, const float* __restrict__ kw)
{
    int s = blockIdx.x, kvh = blockIdx.y, d = threadIdx.x;
    const float* base = g_qkv + (size_t)s * QKVN + kvh * (4 * Dd);
    float cv = cosb[s * Dd + d], sv = sinb[s * Dd + d];
    __shared__ float buf[Dd];
    __shared__ float red[Dd];
    for (int sub = 0; sub < 3; sub++) {
        float x = base[sub * Dd + d];
        buf[d] = x; __syncthreads();
        float rot = (d < 32) ? -buf[d + 32] : buf[d - 32];
        float y = x * cv + rot * sv;
        red[d] = y * y; __syncthreads();
        for (int o = 32; o > 0; o >>= 1) { if (d < o) red[d] += red[d + o]; __syncthreads(); }
        float inv = rsqrtf(red[0] / Dd + 1e-6f);
        float outv = y * inv * (sub < 2 ? qw[d] : kw[d]);
        if (sub < 2) g_q[((size_t)(kvh*2 + sub) * SS + s) * Dd + d] = outv;
        else         g_k[((size_t)kvh * SS + s) * Dd + d] = outv;
        __syncthreads();
    }
    g_vT[((size_t)kvh * Dd + d) * SS + s] = base[3 * Dd + d];
}

// ---------------- causal softmax; zero-fill only the PV-read window ----------------
__global__ void softmax_causal_k()
{
    int q = blockIdx.x, h = blockIdx.y;
    float* row = g_scores + ((size_t)h * SS + q) * SS;
    int n = q + 1;
    int lim = ((q >> 7) + 1) << 7;
    __shared__ float red[256];
    float m = -1e30f;
    for (int i = threadIdx.x; i < n; i += 256) m = fmaxf(m, row[i]);
    red[threadIdx.x] = m; __syncthreads();
    for (int o = 128; o > 0; o >>= 1) { if (threadIdx.x < o) red[threadIdx.x] = fmaxf(red[threadIdx.x], red[threadIdx.x + o]); __syncthreads(); }
    m = red[0]; __syncthreads();
    float sum = 0.f;
    for (int i = threadIdx.x; i < n; i += 256) { float e = expf(row[i] - m); row[i] = e; sum += e; }
    red[threadIdx.x] = sum; __syncthreads();
    for (int o = 128; o > 0; o >>= 1) { if (threadIdx.x < o) red[threadIdx.x] += red[threadIdx.x + o]; __syncthreads(); }
    float inv = 1.f / red[0];
    for (int i = threadIdx.x; i < n; i += 256) row[i] *= inv;
    for (int i = n + threadIdx.x; i < lim; i += 256) row[i] = 0.f;
}

// ---------------- gating: softmax over 64 + top-8 ----------------
__global__ void gate_topk_k()
{
    int s = blockIdx.x, e = threadIdx.x;
    __shared__ float vals[En], red[En];
    float l = g_logits[s * En + e];
    red[e] = l; __syncthreads();
    for (int o = 32; o > 0; o >>= 1) { if (e < o) red[e] = fmaxf(red[e], red[e + o]); __syncthreads(); }
    float mx = red[0]; __syncthreads();
    float g = expf(l - mx);
    red[e] = g; __syncthreads();
    for (int o = 32; o > 0; o >>= 1) { if (e < o) red[e] += red[e + o]; __syncthreads(); }
    float inv = 1.f / red[0]; __syncthreads();
    vals[e] = g * inv; __syncthreads();
    if (e == 0) {
        float tv[Kk]; float sum8 = 0.f; unsigned long long used = 0;
        for (int k = 0; k < Kk; k++) {
            int best = 0; float bv = -1e30f;
            for (int j = 0; j < En; j++)
                if (!((used >> j) & 1ull) && vals[j] > bv) { bv = vals[j]; best = j; }
            used |= 1ull << best;
            g_topi[s * Kk + k] = best; tv[k] = bv; sum8 += bv;
        }
        if (sum8 < F32EPS) sum8 = F32EPS;
        for (int k = 0; k < Kk; k++) g_topw[s * Kk + k] = tv[k] / sum8;
    }
}

// ---------------- deterministic capacity dispatch (warp-parallel, order-preserving) ----------------
__global__ void dispatch_k()
{
    __shared__ int ti[SS * Kk];   // 32 KB
    int tid = threadIdx.x;
    for (int i = tid; i < SS * Kk; i += 1024) ti[i] = g_topi[i];
    __syncthreads();
    int w = tid >> 5, lane = tid & 31;
    unsigned lmask = (1u << lane) - 1u;
    #pragma unroll
    for (int half = 0; half < 2; half++) {
        int e = w + half * 32;
        int cnt = 0;
        for (int k = 0; k < Kk; k++) {
            for (int s0 = 0; s0 < SS; s0 += 32) {
                int s = s0 + lane;
                int match = (ti[s * Kk + k] == e);
                unsigned bal = __ballot_sync(0xFFFFFFFFu, match);
                if (match) {
                    int pos = cnt + __popc(bal & lmask);
                    if (pos < CAPn) { g_etok[e * CAPn + pos] = s; g_slot[s * Kk + k] = pos; }
                    else            g_slot[s * Kk + k] = -1;
                }
                cnt += __popc(bal);
            }
        }
        if (lane == 0) g_ne[e] = cnt < CAPn ? cnt : CAPn;
    }
}

// ---------------- gather tokens per expert, packed bf16 (zero-pad to CAP) ----------------
__global__ void gather_k()
{
    int c = blockIdx.x, e = blockIdx.y;
    uint32_t* dst = g_Xe + ((size_t)e * CAPn + c) * (Hd/2);
    if (c < g_ne[e]) {
        const float* src = g_x2 + (size_t)g_etok[e * CAPn + c] * Hd;
        for (int i = threadIdx.x; i < Hd/2; i += 256)
            dst[i] = pack_bf16(src[2*i], src[2*i + 1]);
    } else {
        for (int i = threadIdx.x; i < Hd/2; i += 256) dst[i] = 0u;
    }
}

// ---------------- final combine ----------------
__global__ void combine_k(float* __restrict__ out)
{
    int s = blockIdx.x, ti = threadIdx.x;
    __shared__ int sl[Kk], ei[Kk];
    __shared__ float wt[Kk];
    if (ti < Kk) { sl[ti] = g_slot[s*Kk+ti]; ei[ti] = g_topi[s*Kk+ti]; wt[ti] = g_topw[s*Kk+ti]; }
    __syncthreads();
    for (int m = ti; m < Hd; m += 256) {
        float acc = g_hidden[(size_t)s * Hd + m] + g_shared[(size_t)s * Hd + m];
        #pragma unroll
        for (int k = 0; k < Kk; k++) {
            int slot = sl[k];
            if (slot >= 0) acc += wt[k] * g_eout[((size_t)ei[k] * CAPn + slot) * Hd + m];
        }
        out[(size_t)s * Hd + m] = acc;
    }
}

// ---------------- host launcher ----------------
extern "C" void kernel_launch(void* const* d_in, const int* in_sizes, int n_in,
                              void* d_out, int out_size)
{
    const float* hs        = (const float*)d_in[0];
    const float* cosb      = (const float*)d_in[1];
    const float* sinb      = (const float*)d_in[2];
    const float* input_lnw = (const float*)d_in[3];
    const float* post_lnw  = (const float*)d_in[4];
    const float* qkv_w     = (const float*)d_in[5];
    const float* o_w       = (const float*)d_in[6];
    const float* q_lnw     = (const float*)d_in[7];
    const float* k_lnw     = (const float*)d_in[8];
    const float* gate_w    = (const float*)d_in[9];
    const float* sgu_w     = (const float*)d_in[10];
    const float* sdown_w   = (const float*)d_in[11];
    const float* egu_w     = (const float*)d_in[12];
    const float* edown_w   = (const float*)d_in[13];
    float* out = (float*)d_out;

    float *p_xnorm, *p_qkv, *p_q, *p_k, *p_vT, *p_scores, *p_attn, *p_hidden,
          *p_x2, *p_act, *p_shared, *p_logits, *p_eout;
    uint32_t *p_Xe, *p_acte;
    int* p_ne;
    cudaGetSymbolAddress((void**)&p_xnorm,  g_xnorm);
    cudaGetSymbolAddress((void**)&p_qkv,    g_qkv);
    cudaGetSymbolAddress((void**)&p_q,      g_q);
    cudaGetSymbolAddress((void**)&p_k,      g_k);
    cudaGetSymbolAddress((void**)&p_vT,     g_vT);
    cudaGetSymbolAddress((void**)&p_scores, g_scores);
    cudaGetSymbolAddress((void**)&p_attn,   g_attn);
    cudaGetSymbolAddress((void**)&p_hidden, g_hidden);
    cudaGetSymbolAddress((void**)&p_x2,     g_x2);
    cudaGetSymbolAddress((void**)&p_act,    g_act);
    cudaGetSymbolAddress((void**)&p_shared, g_shared);
    cudaGetSymbolAddress((void**)&p_logits, g_logits);
    cudaGetSymbolAddress((void**)&p_Xe,     g_Xe);
    cudaGetSymbolAddress((void**)&p_acte,   g_acte);
    cudaGetSymbolAddress((void**)&p_eout,   g_eout);
    cudaGetSymbolAddress((void**)&p_ne,     g_ne);

    static cudaStream_t s2 = nullptr;
    static cudaEvent_t evF = nullptr, evJ = nullptr, evD2 = nullptr;
    static cudaEvent_t evG[4] = {nullptr, nullptr, nullptr, nullptr};
    if (!s2) {
        cudaStreamCreateWithFlags(&s2, cudaStreamNonBlocking);
        cudaEventCreateWithFlags(&evF, cudaEventDisableTiming);
        cudaEventCreateWithFlags(&evJ, cudaEventDisableTiming);
        cudaEventCreateWithFlags(&evD2, cudaEventDisableTiming);
        for (int i = 0; i < 4; i++) cudaEventCreateWithFlags(&evG[i], cudaEventDisableTiming);
    }

    dim3 blk(256);

    // 1) input RMSNorm
    rmsnorm_k<<<SS, blk>>>(hs, input_lnw, p_xnorm);
    // 2) QKV GEMM (tf32 mma)
    gemm_mma<<<dim3(QKVN/128, SS/128, 1), blk>>>(p_xnorm, qkv_w, p_qkv, nullptr,
        Hd, Hd, Hd, QKVN, 1.f, 0,1, 0,1, 0,1, nullptr, 0);
    // 3) split + RoPE + q/k RMSNorm + vT
    rope_split_k<<<dim3(SS, KVHn), Dd>>>(cosb, sinb, q_lnw, k_lnw);
    // 4) scores = q @ k^T / 8 (tf32 mma, causal tile skip)
    gemm_mma<<<dim3(SS/128, SS/128, NHq), blk>>>(p_q, p_k, p_scores, nullptr,
        Dd, Dd, Dd, SS, 0.125f,
        (long long)SS*Dd, 1, (long long)SS*Dd, 2, (long long)SS*SS, 1, nullptr, 1);
    // 5) causal softmax (zero-fill truncated to PV window)
    softmax_causal_k<<<dim3(SS, NHq), blk>>>();
    // 6) attn = P @ V (tf32 mma, causal K truncation)
    gemm_pv<<<dim3(1, SS/128, NHq), blk>>>(p_scores, p_vT, p_attn,
        SS, SS, SS, HQn,
        (long long)SS*SS, (long long)Dd*SS, (long long)Dd);
    // 7) O-proj + residual (tf32 mma)
    gemm_mma<<<dim3(Hd/128, SS/128, 1), blk>>>(p_attn, o_w, p_hidden, hs,
        HQn, HQn, HQn, Hd, 1.f, 0,1, 0,1, 0,1, nullptr, 0);
    // 8) post RMSNorm
    rmsnorm_k<<<SS, blk>>>(p_hidden, post_lnw, p_x2);

    // ---- fork (R9 topology): gating chain on s2 overlaps shared MLP (default) ----
    cudaEventRecord(evF, 0);
    cudaStreamWaitEvent(s2, evF, 0);

    gemm_nt<<<dim3(En/64, SS/64, 1), blk, 0, s2>>>(p_x2, gate_w, p_logits, nullptr,
        SS, En, Hd, Hd, Hd, En, 1.f, 0,1, 0,1, 0,1, nullptr, 0);
    gate_topk_k<<<SS, En, 0, s2>>>();
    dispatch_k<<<1, 1024, 0, s2>>>();
    gather_k<<<dim3(CAPn, En), blk, 0, s2>>>();
    cudaEventRecord(evJ, s2);

    gemm_guact_tf32<<<dim3(FFn/64, SS/128, 1), blk>>>(p_x2, sgu_w, p_act,
        Hd, Hd, Hd, FFn, FFn);
    gemm_mma<<<dim3(Hd/128, SS/128, 1), blk>>>(p_act, sdown_w, p_shared, nullptr,
        FFn, FFn, FFn, Hd, 1.f, 0,1, 0,1, 0,1, nullptr, 0);

    cudaStreamWaitEvent(0, evJ, 0);
    // ---- join ----

    const long long sXe2 = (long long)CAPn*Hd/2;
    const long long sGu  = (long long)2*FFn*Hd;
    const long long sAc2 = (long long)CAPn*FFn/2;
    const long long sDn  = (long long)Hd*FFn;
    const long long sEo  = (long long)CAPn*Hd;
    const int NCH = 4;          // expert chunks
    const int EC = En / NCH;    // 16 experts per chunk

    // pipeline: default runs guact chunks 0..3 then down chunk 3;
    // s2 runs down chunks 0..2, each gated on its guact event.
    for (int ch = 0; ch < NCH; ch++) {
        gemm_guact_bf16<<<dim3(FFn/64, CAPn/128, EC), blk>>>(
            p_Xe + (long long)ch*EC*sXe2, egu_w + (long long)ch*EC*sGu,
            p_acte + (long long)ch*EC*sAc2,
            Hd, Hd/2, Hd, FFn/2, FFn, sXe2, sGu, sAc2, p_ne + ch*EC);
        cudaEventRecord(evG[ch], 0);
        if (ch < NCH - 1) {
            cudaStreamWaitEvent(s2, evG[ch], 0);
            gemm_bf16_abf<<<dim3(Hd/128, CAPn/128, EC), blk, 0, s2>>>(
                p_acte + (long long)ch*EC*sAc2, edown_w + (long long)ch*EC*sDn,
                p_eout + (long long)ch*EC*sEo,
                FFn, FFn/2, FFn, Hd, sAc2, sDn, sEo, p_ne + ch*EC);
        }
    }
    cudaEventRecord(evD2, s2);

    // default: last down chunk
    {
        int ch = NCH - 1;
        gemm_bf16_abf<<<dim3(Hd/128, CAPn/128, EC), blk>>>(
            p_acte + (long long)ch*EC*sAc2, edown_w + (long long)ch*EC*sDn,
            p_eout + (long long)ch*EC*sEo,
            FFn, FFn/2, FFn, Hd, sAc2, sDn, sEo, p_ne + ch*EC);
    }

    cudaStreamWaitEvent(0, evD2, 0);
    // combine -> output
    combine_k<<<SS, blk>>>(out);
}

// round 14
// speedup vs baseline: 1.1905x; 1.1905x over previous
#include <cuda_runtime.h>
#include <math.h>
#include <stdint.h>

#define SS    1024
#define Hd    768
#define NHq   16
#define KVHn  8
#define Dd    64
#define HQn   (NHq*Dd)        // 1024
#define QKVN  (HQn + 2*KVHn*Dd) // 2048
#define En    64
#define Kk    8
#define FFn   3072
#define CAPn  256
#define F32EPS 1.1920929e-07f

// ---------------- scratch (device globals; no allocation) ----------------
__device__ float g_xnorm[SS*Hd];
__device__ float g_qkv[SS*QKVN];
__device__ float g_q[NHq*SS*Dd];
__device__ float g_k[KVHn*SS*Dd];
__device__ float g_vT[KVHn*Dd*SS];
__device__ float g_scores[(size_t)NHq*SS*SS];
__device__ float g_attn[SS*HQn];
__device__ float g_hidden[SS*Hd];
__device__ float g_x2[SS*Hd];
__device__ float g_act[SS*FFn];
__device__ float g_shared[SS*Hd];
__device__ float g_logits[SS*En];
__device__ int   g_topi[SS*Kk];
__device__ float g_topw[SS*Kk];
__device__ int   g_slot[SS*Kk];
__device__ int   g_etok[En*CAPn];
__device__ int   g_ne[En];
__device__ uint32_t g_Xe[(size_t)En*CAPn*Hd/2];        // bf16x2 packed
__device__ uint32_t g_acte[(size_t)En*CAPn*FFn/2];     // bf16x2 packed
__device__ float g_eout[(size_t)En*CAPn*Hd];
__device__ uint32_t g_eguw[(size_t)En*FFn*Hd];         // egu_w  bf16x2 (604 MB)
__device__ uint32_t g_ednw[(size_t)En*Hd*FFn/2];       // edown_w bf16x2 (302 MB)

// ================= mma helpers (portable PTX, no 'a' features) =================
__device__ __forceinline__ uint32_t cvt_tf32(float f) {
    uint32_t u;
    asm("cvt.rna.tf32.f32 %0, %1;" : "=r"(u) : "f"(f));
    return u;
}

__device__ __forceinline__ void mma_tf32(float* c, const uint32_t* a, uint32_t b0, uint32_t b1) {
    asm volatile(
        "mma.sync.aligned.m16n8k8.row.col.f32.tf32.tf32.f32 "
        "{%0,%1,%2,%3}, {%4,%5,%6,%7}, {%8,%9}, {%0,%1,%2,%3};"
        : "+f"(c[0]), "+f"(c[1]), "+f"(c[2]), "+f"(c[3])
        : "r"(a[0]), "r"(a[1]), "r"(a[2]), "r"(a[3]), "r"(b0), "r"(b1));
}

__device__ __forceinline__ void mma_bf16(float* c, const uint32_t* a, uint32_t b0, uint32_t b1) {
    asm volatile(
        "mma.sync.aligned.m16n8k16.row.col.f32.bf16.bf16.f32 "
        "{%0,%1,%2,%3}, {%4,%5,%6,%7}, {%8,%9}, {%0,%1,%2,%3};"
        : "+f"(c[0]), "+f"(c[1]), "+f"(c[2]), "+f"(c[3])
        : "r"(a[0]), "r"(a[1]), "r"(a[2]), "r"(a[3]), "r"(b0), "r"(b1));
}

__device__ __forceinline__ uint32_t pack_bf16(float lo, float hi) {
    uint32_t r;
    asm("cvt.rn.bf16x2.f32 %0, %1, %2;" : "=r"(r) : "f"(hi), "f"(lo));
    return r;
}

__device__ __forceinline__ void ldsm_x4(uint32_t& d0, uint32_t& d1, uint32_t& d2, uint32_t& d3,
                                        uint32_t addr) {
    asm volatile("ldmatrix.sync.aligned.m8n8.x4.shared.b16 {%0,%1,%2,%3}, [%4];"
                 : "=r"(d0), "=r"(d1), "=r"(d2), "=r"(d3) : "r"(addr));
}

__device__ __forceinline__ void cp_async16(uint32_t dst, const void* src) {
    asm volatile("cp.async.cg.shared.global [%0], [%1], 16;" :: "r"(dst), "l"(src) : "memory");
}
#define CP_COMMIT() asm volatile("cp.async.commit_group;" ::: "memory")
#define CP_WAIT0()  asm volatile("cp.async.wait_group 0;" ::: "memory")

__device__ __forceinline__ float silu_f(float x) {
    return x / (1.f + expf(-x));
}

// ---------------- weight fp32 -> packed bf16 conversion (hidden under attention) ----------------
__global__ void cvtw_k(const float* __restrict__ in, uint32_t* __restrict__ out, long long n4)
{
    long long i = (long long)blockIdx.x * 256 + threadIdx.x;
    if (i >= n4) return;
    float4 a = *(const float4*)(in + 8*i);
    float4 b = *(const float4*)(in + 8*i + 4);
    uint4 o;
    o.x = pack_bf16(a.x, a.y); o.y = pack_bf16(a.z, a.w);
    o.z = pack_bf16(b.x, b.y); o.w = pack_bf16(b.z, b.w);
    *(uint4*)(out + 4*i) = o;
}

// ============ tf32 tensor-core NT GEMM: C[z][128m,128n] = alpha*A@B^T (+res) ============
__global__ void __launch_bounds__(256)
gemm_mma(const float* __restrict__ A, const float* __restrict__ B,
         float* __restrict__ C, const float* __restrict__ res,
         int Kd, int lda, int ldb, int ldc, float alpha,
         long long sA, int dA, long long sB, int dB, long long sC, int dC,
         const int* __restrict__ rowLim, int causal)
{
    int z = blockIdx.z;
    int row0 = blockIdx.y * 128, col0 = blockIdx.x * 128;
    if (rowLim && row0 >= rowLim[z]) return;
    if (causal && col0 > row0 + 127) return;
    A += (long long)(z / dA) * sA;
    B += (long long)(z / dB) * sB;
    C += (long long)(z / dC) * sC;

    __shared__ uint32_t As[128][36];
    __shared__ uint32_t Bs[128][36];

    int tid = threadIdx.x;
    int wid = tid >> 5, lane = tid & 31;
    int wm = wid & 3, wn = wid >> 2;
    int g = lane >> 2, t = lane & 3;

    int crow = tid >> 1;
    int ckb = (tid & 1) * 16;
    const float* Ag = A + (size_t)(row0 + crow) * lda + ckb;
    const float* Bg = B + (size_t)(col0 + crow) * ldb + ckb;

    float acc[2][8][4];
    #pragma unroll
    for (int mt = 0; mt < 2; mt++)
        #pragma unroll
        for (int nt = 0; nt < 8; nt++)
            #pragma unroll
            for (int i = 0; i < 4; i++) acc[mt][nt][i] = 0.f;

    const int NC = Kd / 32;
    float4 av[4], bv[4];

    #pragma unroll
    for (int i = 0; i < 4; i++) {
        av[i] = *(const float4*)(Ag + i*4);
        bv[i] = *(const float4*)(Bg + i*4);
    }

    for (int c = 0; ; ) {
        #pragma unroll
        for (int i = 0; i < 4; i++) {
            uint4 pa, pb;
            pa.x = cvt_tf32(av[i].x); pa.y = cvt_tf32(av[i].y);
            pa.z = cvt_tf32(av[i].z); pa.w = cvt_tf32(av[i].w);
            pb.x = cvt_tf32(bv[i].x); pb.y = cvt_tf32(bv[i].y);
            pb.z = cvt_tf32(bv[i].z); pb.w = cvt_tf32(bv[i].w);
            *(uint4*)&As[crow][ckb + i*4] = pa;
            *(uint4*)&Bs[crow][ckb + i*4] = pb;
        }
        __syncthreads();

        bool more = (c + 1 < NC);
        if (more) {
            size_t off = (size_t)(c + 1) * 32;
            #pragma unroll
            for (int i = 0; i < 4; i++) {
                av[i] = *(const float4*)(Ag + off + i*4);
                bv[i] = *(const float4*)(Bg + off + i*4);
            }
        }

        #pragma unroll
        for (int ks = 0; ks < 4; ks++) {
            int k8 = ks * 8;
            uint32_t a[2][4];
            #pragma unroll
            for (int mt = 0; mt < 2; mt++) {
                int m = wm*32 + mt*16;
                a[mt][0] = As[m + g    ][k8 + t    ];
                a[mt][1] = As[m + g + 8][k8 + t    ];
                a[mt][2] = As[m + g    ][k8 + t + 4];
                a[mt][3] = As[m + g + 8][k8 + t + 4];
            }
            #pragma unroll
            for (int nt = 0; nt < 8; nt++) {
                int n = wn*64 + nt*8;
                uint32_t b0 = Bs[n + g][k8 + t];
                uint32_t b1 = Bs[n + g][k8 + t + 4];
                #pragma unroll
                for (int mt = 0; mt < 2; mt++)
                    mma_tf32(acc[mt][nt], a[mt], b0, b1);
            }
        }

        c++;
        if (!more) break;
        __syncthreads();
    }

    #pragma unroll
    for (int mt = 0; mt < 2; mt++) {
        int r0 = row0 + wm*32 + mt*16 + g;
        #pragma unroll
        for (int nt = 0; nt < 8; nt++) {
            int cc = col0 + wn*64 + nt*8 + t*2;
            float2 v0, v1;
            v0.x = alpha * acc[mt][nt][0];
            v0.y = alpha * acc[mt][nt][1];
            v1.x = alpha * acc[mt][nt][2];
            v1.y = alpha * acc[mt][nt][3];
            if (res) {
                float2 r0v = *(const float2*)&res[(size_t)r0 * ldc + cc];
                float2 r1v = *(const float2*)&res[(size_t)(r0+8) * ldc + cc];
                v0.x += r0v.x; v0.y += r0v.y;
                v1.x += r1v.x; v1.y += r1v.y;
            }
            *(float2*)&C[(size_t)r0 * ldc + cc] = v0;
            *(float2*)&C[(size_t)(r0+8) * ldc + cc] = v1;
        }
    }
}

// ============ tf32 fused gu GEMM + SwiGLU (shared MLP): Out[128m, 64ac] ============
__global__ void __launch_bounds__(256)
gemm_guact_tf32(const float* __restrict__ A, const float* __restrict__ B,
                float* __restrict__ Out,
                int Kd, int lda, int ldb, int ldout, int ffrows)
{
    int row0 = blockIdx.y * 128;
    int colact0 = blockIdx.x * 64;

    __shared__ uint32_t As[128][36];
    __shared__ uint32_t Bs[128][36];

    int tid = threadIdx.x;
    int wid = tid >> 5, lane = tid & 31;
    int wm = wid & 3, wn = wid >> 2;
    int g = lane >> 2, t = lane & 3;

    int crow = tid >> 1;
    int ckb = (tid & 1) * 16;
    const float* Ag = A + (size_t)(row0 + crow) * lda + ckb;
    int blk = crow >> 6, h = (crow >> 5) & 1, inner = crow & 31;
    int brow = h * ffrows + colact0 + blk * 32 + inner;
    const float* Bg = B + (size_t)brow * ldb + ckb;

    float acc[2][8][4];
    #pragma unroll
    for (int mt = 0; mt < 2; mt++)
        #pragma unroll
        for (int nt = 0; nt < 8; nt++)
            #pragma unroll
            for (int i = 0; i < 4; i++) acc[mt][nt][i] = 0.f;

    const int NC = Kd / 32;
    float4 av[4], bv[4];
    #pragma unroll
    for (int i = 0; i < 4; i++) {
        av[i] = *(const float4*)(Ag + i*4);
        bv[i] = *(const float4*)(Bg + i*4);
    }

    for (int c = 0; ; ) {
        #pragma unroll
        for (int i = 0; i < 4; i++) {
            uint4 pa, pb;
            pa.x = cvt_tf32(av[i].x); pa.y = cvt_tf32(av[i].y);
            pa.z = cvt_tf32(av[i].z); pa.w = cvt_tf32(av[i].w);
            pb.x = cvt_tf32(bv[i].x); pb.y = cvt_tf32(bv[i].y);
            pb.z = cvt_tf32(bv[i].z); pb.w = cvt_tf32(bv[i].w);
            *(uint4*)&As[crow][ckb + i*4] = pa;
            *(uint4*)&Bs[crow][ckb + i*4] = pb;
        }
        __syncthreads();

        bool more = (c + 1 < NC);
        if (more) {
            size_t off = (size_t)(c + 1) * 32;
            #pragma unroll
            for (int i = 0; i < 4; i++) {
                av[i] = *(const float4*)(Ag + off + i*4);
                bv[i] = *(const float4*)(Bg + off + i*4);
            }
        }

        #pragma unroll
        for (int ks = 0; ks < 4; ks++) {
            int k8 = ks * 8;
            uint32_t a[2][4];
            #pragma unroll
            for (int mt = 0; mt < 2; mt++) {
                int m = wm*32 + mt*16;
                a[mt][0] = As[m + g    ][k8 + t    ];
                a[mt][1] = As[m + g + 8][k8 + t    ];
                a[mt][2] = As[m + g    ][k8 + t + 4];
                a[mt][3] = As[m + g + 8][k8 + t + 4];
            }
            #pragma unroll
            for (int nt = 0; nt < 8; nt++) {
                int n = wn*64 + nt*8;
                uint32_t b0 = Bs[n + g][k8 + t];
                uint32_t b1 = Bs[n + g][k8 + t + 4];
                #pragma unroll
                for (int mt = 0; mt < 2; mt++)
                    mma_tf32(acc[mt][nt], a[mt], b0, b1);
            }
        }

        c++;
        if (!more) break;
        __syncthreads();
    }

    #pragma unroll
    for (int mt = 0; mt < 2; mt++) {
        int r0 = row0 + wm*32 + mt*16 + g;
        #pragma unroll
        for (int j = 0; j < 4; j++) {
            int ac = colact0 + wn*32 + j*8 + t*2;
            float2 v0, v1;
            v0.x = acc[mt][j][0] * silu_f(acc[mt][j+4][0]);
            v0.y = acc[mt][j][1] * silu_f(acc[mt][j+4][1]);
            v1.x = acc[mt][j][2] * silu_f(acc[mt][j+4][2]);
            v1.y = acc[mt][j][3] * silu_f(acc[mt][j+4][3]);
            *(float2*)&Out[(size_t)r0 * ldout + ac] = v0;
            *(float2*)&Out[(size_t)(r0+8) * ldout + ac] = v1;
        }
    }
}

// ============ tf32 PV GEMM: C[z][128m, 64n] = A[z]@B[z/2]^T, causal K-truncated ============
__global__ void __launch_bounds__(256)
gemm_pv(const float* __restrict__ A, const float* __restrict__ B,
        float* __restrict__ C, int Kd, int lda, int ldb, int ldc,
        long long sA, long long sB, long long sC)
{
    int z = blockIdx.z;
    int row0 = blockIdx.y * 128;
    A += (long long)z * sA;
    B += (long long)(z >> 1) * sB;
    C += (long long)z * sC;

    __shared__ uint32_t As[128][36];
    __shared__ uint32_t Bs[64][36];

    int tid = threadIdx.x;
    int wid = tid >> 5, lane = tid & 31;
    int wm = wid & 3, wn = wid >> 2;
    int g = lane >> 2, t = lane & 3;

    int crow = tid >> 1;
    int ckb = (tid & 1) * 16;
    const float* Ag = A + (size_t)(row0 + crow) * lda + ckb;
    const float* Bg = B + (size_t)(tid >> 2) * ldb + (tid & 3) * 8;

    float acc[2][4][4];
    #pragma unroll
    for (int mt = 0; mt < 2; mt++)
        #pragma unroll
        for (int nt = 0; nt < 4; nt++)
            #pragma unroll
            for (int i = 0; i < 4; i++) acc[mt][nt][i] = 0.f;

    int KdEff = row0 + 128;
    if (KdEff > Kd) KdEff = Kd;
    const int NC = KdEff / 32;

    float4 av[4], bv[2];
    #pragma unroll
    for (int i = 0; i < 4; i++) av[i] = *(const float4*)(Ag + i*4);
    #pragma unroll
    for (int i = 0; i < 2; i++) bv[i] = *(const float4*)(Bg + i*4);

    for (int c = 0; ; ) {
        #pragma unroll
        for (int i = 0; i < 4; i++) {
            uint4 pa;
            pa.x = cvt_tf32(av[i].x); pa.y = cvt_tf32(av[i].y);
            pa.z = cvt_tf32(av[i].z); pa.w = cvt_tf32(av[i].w);
            *(uint4*)&As[crow][ckb + i*4] = pa;
        }
        #pragma unroll
        for (int i = 0; i < 2; i++) {
            uint4 pb;
            pb.x = cvt_tf32(bv[i].x); pb.y = cvt_tf32(bv[i].y);
            pb.z = cvt_tf32(bv[i].z); pb.w = cvt_tf32(bv[i].w);
            *(uint4*)&Bs[tid >> 2][(tid & 3) * 8 + i*4] = pb;
        }
        __syncthreads();

        bool more = (c + 1 < NC);
        if (more) {
            size_t off = (size_t)(c + 1) * 32;
            #pragma unroll
            for (int i = 0; i < 4; i++) av[i] = *(const float4*)(Ag + off + i*4);
            #pragma unroll
            for (int i = 0; i < 2; i++) bv[i] = *(const float4*)(Bg + off + i*4);
        }

        #pragma unroll
        for (int ks = 0; ks < 4; ks++) {
            int k8 = ks * 8;
            uint32_t a[2][4];
            #pragma unroll
            for (int mt = 0; mt < 2; mt++) {
                int m = wm*32 + mt*16;
                a[mt][0] = As[m + g    ][k8 + t    ];
                a[mt][1] = As[m + g + 8][k8 + t    ];
                a[mt][2] = As[m + g    ][k8 + t + 4];
                a[mt][3] = As[m + g + 8][k8 + t + 4];
            }
            #pragma unroll
            for (int nt = 0; nt < 4; nt++) {
                int n = wn*32 + nt*8;
                uint32_t b0 = Bs[n + g][k8 + t];
                uint32_t b1 = Bs[n + g][k8 + t + 4];
                #pragma unroll
                for (int mt = 0; mt < 2; mt++)
                    mma_tf32(acc[mt][nt], a[mt], b0, b1);
            }
        }

        c++;
        if (!more) break;
        __syncthreads();
    }

    #pragma unroll
    for (int mt = 0; mt < 2; mt++) {
        int r0 = row0 + wm*32 + mt*16 + g;
        #pragma unroll
        for (int nt = 0; nt < 4; nt++) {
            int cc = wn*32 + nt*8 + t*2;
            float2 v0, v1;
            v0.x = acc[mt][nt][0]; v0.y = acc[mt][nt][1];
            v1.x = acc[mt][nt][2]; v1.y = acc[mt][nt][3];
            *(float2*)&C[(size_t)r0 * ldc + cc] = v0;
            *(float2*)&C[(size_t)(r0+8) * ldc + cc] = v1;
        }
    }
}

// ============ bf16 fused expert gu GEMM + SwiGLU; A and B packed bf16, cp.async ============
__global__ void __launch_bounds__(256, 2)
gemm_guact_bf16(const uint32_t* __restrict__ A, const uint32_t* __restrict__ B,
                uint32_t* __restrict__ Out,
                int Kd, int ldau2, int ldb2, int ldout2, int ffrows,
                long long sA2, long long sB2, long long sOut2,
                const int* __restrict__ rowLim)
{
    int z = blockIdx.z;
    int row0 = blockIdx.y * 128;
    if (rowLim && row0 >= rowLim[z]) return;
    int colact0 = blockIdx.x * 64;
    A   += (long long)z * sA2;
    B   += (long long)z * sB2;
    Out += (long long)z * sOut2;

    __shared__ uint32_t Asu[2][128][20];
    __shared__ uint32_t Bsu[2][128][20];

    int tid = threadIdx.x;
    int wid = tid >> 5, lane = tid & 31;
    int wm = wid & 3, wn = wid >> 2;
    int g = lane >> 2, t = lane & 3;
    int mi = lane >> 3, r = lane & 7;

    int crow = tid >> 1;
    int kh = tid & 1;
    const uint32_t* Ag = A + (size_t)(row0 + crow) * ldau2 + kh * 8;
    int blk = crow >> 6, h = (crow >> 5) & 1, inner = crow & 31;
    int brow = h * ffrows + colact0 + blk * 32 + inner;
    const uint32_t* Bg = B + (size_t)brow * ldb2 + kh * 8;

    uint32_t aDst[2], bDst[2];
    aDst[0] = (uint32_t)__cvta_generic_to_shared(&Asu[0][crow][kh*8]);
    aDst[1] = (uint32_t)__cvta_generic_to_shared(&Asu[1][crow][kh*8]);
    bDst[0] = (uint32_t)__cvta_generic_to_shared(&Bsu[0][crow][kh*8]);
    bDst[1] = (uint32_t)__cvta_generic_to_shared(&Bsu[1][crow][kh*8]);

    uint32_t aAddr[2][2], bAddr[2][4];
    #pragma unroll
    for (int buf = 0; buf < 2; buf++) {
        #pragma unroll
        for (int mt = 0; mt < 2; mt++) {
            int rowA = wm*32 + mt*16 + (mi & 1)*8 + r;
            aAddr[buf][mt] = (uint32_t)__cvta_generic_to_shared(&Asu[buf][rowA][(mi >> 1)*4]);
        }
        #pragma unroll
        for (int ntp = 0; ntp < 4; ntp++) {
            int rowB = wn*64 + ntp*16 + (mi >> 1)*8 + r;
            bAddr[buf][ntp] = (uint32_t)__cvta_generic_to_shared(&Bsu[buf][rowB][(mi & 1)*4]);
        }
    }

    float acc[2][8][4];
    #pragma unroll
    for (int mt = 0; mt < 2; mt++)
        #pragma unroll
        for (int j = 0; j < 8; j++)
            #pragma unroll
            for (int i = 0; i < 4; i++) acc[mt][j][i] = 0.f;

    const int NC = Kd / 32;

    cp_async16(aDst[0], Ag);
    cp_async16(aDst[0] + 16, Ag + 4);
    cp_async16(bDst[0], Bg);
    cp_async16(bDst[0] + 16, Bg + 4);
    CP_COMMIT();
    CP_WAIT0();
    __syncthreads();

    for (int c = 0; c < NC; c++) {
        int buf = c & 1;
        bool more = (c + 1 < NC);
        if (more) {
            int nb = buf ^ 1;
            const uint32_t* Agc = Ag + (size_t)(c + 1) * 16;
            const uint32_t* Bgc = Bg + (size_t)(c + 1) * 16;
            cp_async16(aDst[nb], Agc);
            cp_async16(aDst[nb] + 16, Agc + 4);
            cp_async16(bDst[nb], Bgc);
            cp_async16(bDst[nb] + 16, Bgc + 4);
            CP_COMMIT();
        }
        #pragma unroll
        for (int ks = 0; ks < 2; ks++) {
            uint32_t afr[2][4];
            #pragma unroll
            for (int mt = 0; mt < 2; mt++)
                ldsm_x4(afr[mt][0], afr[mt][1], afr[mt][2], afr[mt][3],
                        aAddr[buf][mt] + ks*32);
            #pragma unroll
            for (int ntp = 0; ntp < 4; ntp++) {
                uint32_t b00, b01, b10, b11;
                ldsm_x4(b00, b01, b10, b11, bAddr[buf][ntp] + ks*32);
                #pragma unroll
                for (int mt = 0; mt < 2; mt++) {
                    mma_bf16(acc[mt][2*ntp  ], afr[mt], b00, b01);
                    mma_bf16(acc[mt][2*ntp+1], afr[mt], b10, b11);
                }
            }
        }
        if (more) {
            CP_WAIT0();
            __syncthreads();
        }
    }

    // SwiGLU epilogue: j<4 = x1, j>=4 = x2; write packed bf16x2
    #pragma unroll
    for (int mt = 0; mt < 2; mt++) {
        int r0 = row0 + wm*32 + mt*16 + g;
        #pragma unroll
        for (int j = 0; j < 4; j++) {
            int ac = colact0 + wn*32 + j*8 + t*2;
            float v0x = acc[mt][j][0] * silu_f(acc[mt][j+4][0]);
            float v0y = acc[mt][j][1] * silu_f(acc[mt][j+4][1]);
            float v1x = acc[mt][j][2] * silu_f(acc[mt][j+4][2]);
            float v1y = acc[mt][j][3] * silu_f(acc[mt][j+4][3]);
            Out[(size_t)r0 * ldout2 + (ac >> 1)] = pack_bf16(v0x, v0y);
            Out[(size_t)(r0+8) * ldout2 + (ac >> 1)] = pack_bf16(v1x, v1y);
        }
    }
}

// ============ bf16 NT GEMM, A and B packed bf16, cp.async: C[z][128m,128n] = A@B^T ============
__global__ void __launch_bounds__(256, 2)
gemm_bf16_ab(const uint32_t* __restrict__ A, const uint32_t* __restrict__ B,
             float* __restrict__ C,
             int Kd, int ldau2, int ldb2, int ldc,
             long long sA2, long long sB2, long long sC,
             const int* __restrict__ rowLim)
{
    int z = blockIdx.z;
    int row0 = blockIdx.y * 128, col0 = blockIdx.x * 128;
    if (rowLim && row0 >= rowLim[z]) return;
    A += (long long)z * sA2;
    B += (long long)z * sB2;
    C += (long long)z * sC;

    __shared__ uint32_t Asu[2][128][20];
    __shared__ uint32_t Bsu[2][128][20];

    int tid = threadIdx.x;
    int wid = tid >> 5, lane = tid & 31;
    int wm = wid & 3, wn = wid >> 2;
    int g = lane >> 2, t = lane & 3;
    int mi = lane >> 3, r = lane & 7;

    int crow = tid >> 1;
    int kh = tid & 1;
    const uint32_t* Ag = A + (size_t)(row0 + crow) * ldau2 + kh * 8;
    const uint32_t* Bg = B + (size_t)(col0 + crow) * ldb2 + kh * 8;

    uint32_t aDst[2], bDst[2];
    aDst[0] = (uint32_t)__cvta_generic_to_shared(&Asu[0][crow][kh*8]);
    aDst[1] = (uint32_t)__cvta_generic_to_shared(&Asu[1][crow][kh*8]);
    bDst[0] = (uint32_t)__cvta_generic_to_shared(&Bsu[0][crow][kh*8]);
    bDst[1] = (uint32_t)__cvta_generic_to_shared(&Bsu[1][crow][kh*8]);

    uint32_t aAddr[2][2], bAddr[2][4];
    #pragma unroll
    for (int buf = 0; buf < 2; buf++) {
        #pragma unroll
        for (int mt = 0; mt < 2; mt++) {
            int rowA = wm*32 + mt*16 + (mi & 1)*8 + r;
            aAddr[buf][mt] = (uint32_t)__cvta_generic_to_shared(&Asu[buf][rowA][(mi >> 1)*4]);
        }
        #pragma unroll
        for (int ntp = 0; ntp < 4; ntp++) {
            int rowB = wn*64 + ntp*16 + (mi >> 1)*8 + r;
            bAddr[buf][ntp] = (uint32_t)__cvta_generic_to_shared(&Bsu[buf][rowB][(mi & 1)*4]);
        }
    }

    float acc[2][8][4];
    #pragma unroll
    for (int mt = 0; mt < 2; mt++)
        #pragma unroll
        for (int j = 0; j < 8; j++)
            #pragma unroll
            for (int i = 0; i < 4; i++) acc[mt][j][i] = 0.f;

    const int NC = Kd / 32;

    cp_async16(aDst[0], Ag);
    cp_async16(aDst[0] + 16, Ag + 4);
    cp_async16(bDst[0], Bg);
    cp_async16(bDst[0] + 16, Bg + 4);
    CP_COMMIT();
    CP_WAIT0();
    __syncthreads();

    for (int c = 0; c < NC; c++) {
        int buf = c & 1;
        bool more = (c + 1 < NC);
        if (more) {
            int nb = buf ^ 1;
            const uint32_t* Agc = Ag + (size_t)(c + 1) * 16;
            const uint32_t* Bgc = Bg + (size_t)(c + 1) * 16;
            cp_async16(aDst[nb], Agc);
            cp_async16(aDst[nb] + 16, Agc + 4);
            cp_async16(bDst[nb], Bgc);
            cp_async16(bDst[nb] + 16, Bgc + 4);
            CP_COMMIT();
        }
        #pragma unroll
        for (int ks = 0; ks < 2; ks++) {
            uint32_t afr[2][4];
            #pragma unroll
            for (int mt = 0; mt < 2; mt++)
                ldsm_x4(afr[mt][0], afr[mt][1], afr[mt][2], afr[mt][3],
                        aAddr[buf][mt] + ks*32);
            #pragma unroll
            for (int ntp = 0; ntp < 4; ntp++) {
                uint32_t b00, b01, b10, b11;
                ldsm_x4(b00, b01, b10, b11, bAddr[buf][ntp] + ks*32);
                #pragma unroll
                for (int mt = 0; mt < 2; mt++) {
                    mma_bf16(acc[mt][2*ntp  ], afr[mt], b00, b01);
                    mma_bf16(acc[mt][2*ntp+1], afr[mt], b10, b11);
                }
            }
        }
        if (more) {
            CP_WAIT0();
            __syncthreads();
        }
    }

    #pragma unroll
    for (int mt = 0; mt < 2; mt++) {
        int r0 = row0 + wm*32 + mt*16 + g;
        #pragma unroll
        for (int j = 0; j < 8; j++) {
            int cc = col0 + wn*64 + j*8 + t*2;
            float2 v0, v1;
            v0.x = acc[mt][j][0]; v0.y = acc[mt][j][1];
            v1.x = acc[mt][j][2]; v1.y = acc[mt][j][3];
            *(float2*)&C[(size_t)r0 * ldc + cc] = v0;
            *(float2*)&C[(size_t)(r0+8) * ldc + cc] = v1;
        }
    }
}

// ================= generic 64x64 fp32 NT GEMM (router logits) =================
__global__ void gemm_nt(const float* __restrict__ A, const float* __restrict__ B,
                        float* __restrict__ C, const float* __restrict__ res,
                        int M, int N, int Kd, int lda, int ldb, int ldc, float alpha,
                        long long sA, int dA, long long sB, int dB, long long sC, int dC,
                        const int* __restrict__ rowLim, int causal)
{
    int z = blockIdx.z;
    int row0 = blockIdx.y * 64, col0 = blockIdx.x * 64;
    if (rowLim && row0 >= rowLim[z]) return;
    if (causal && col0 > row0 + 63) return;
    A += (long long)(z / dA) * sA;
    B += (long long)(z / dB) * sB;
    C += (long long)(z / dC) * sC;

    __shared__ float As[16][64];
    __shared__ float Bs[16][64];
    int tid = threadIdx.x;
    int tr = tid >> 2;
    int tk = (tid & 3) * 4;
    int ty = tid >> 4, tx = tid & 15;

    float c[4][4] = {};
    for (int k0 = 0; k0 < Kd; k0 += 16) {
        float4 a4 = *(const float4*)&A[(size_t)(row0 + tr) * lda + k0 + tk];
        float4 b4 = *(const float4*)&B[(size_t)(col0 + tr) * ldb + k0 + tk];
        As[tk+0][tr] = a4.x; As[tk+1][tr] = a4.y; As[tk+2][tr] = a4.z; As[tk+3][tr] = a4.w;
        Bs[tk+0][tr] = b4.x; Bs[tk+1][tr] = b4.y; Bs[tk+2][tr] = b4.z; Bs[tk+3][tr] = b4.w;
        __syncthreads();
        #pragma unroll
        for (int k = 0; k < 16; k++) {
            float a[4], b[4];
            #pragma unroll
            for (int i = 0; i < 4; i++) a[i] = As[k][ty*4 + i];
            #pragma unroll
            for (int j = 0; j < 4; j++) b[j] = Bs[k][tx*4 + j];
            #pragma unroll
            for (int i = 0; i < 4; i++)
                #pragma unroll
                for (int j = 0; j < 4; j++)
                    c[i][j] += a[i] * b[j];
        }
        __syncthreads();
    }
    #pragma unroll
    for (int i = 0; i < 4; i++) {
        int r = row0 + ty*4 + i;
        #pragma unroll
        for (int j = 0; j < 4; j++) {
            int cc = col0 + tx*4 + j;
            float v = alpha * c[i][j];
            if (res) v += res[(size_t)r * ldc + cc];
            C[(size_t)r * ldc + cc] = v;
        }
    }
}

// ---------------- RMSNorm over H=768 ----------------
__global__ void rmsnorm_k(const float* __restrict__ x, const float* __restrict__ w,
                          float* __restrict__ out)
{
    int s = blockIdx.x;
    const float* row = x + (size_t)s * Hd;
    __shared__ float red[256];
    float acc = 0.f;
    for (int i = threadIdx.x; i < Hd; i += 256) { float v = row[i]; acc += v * v; }
    red[threadIdx.x] = acc; __syncthreads();
    for (int o = 128; o > 0; o >>= 1) { if (threadIdx.x < o) red[threadIdx.x] += red[threadIdx.x + o]; __syncthreads(); }
    float inv = rsqrtf(red[0] / Hd + 1e-6f);
    for (int i = threadIdx.x; i < Hd; i += 256) out[(size_t)s * Hd + i] = w[i] * row[i] * inv;
}

// ---------------- split qkv + RoPE + per-head RMSNorm + v transpose ----------------
__global__ void rope_split_k(const float* __restrict__ cosb, const float* __restrict__ sinb,
                             const float* __restrict__ qw, const float* __restrict__ kw)
{
    int s = blockIdx.x, kvh = blockIdx.y, d = threadIdx.x;
    const float* base = g_qkv + (size_t)s * QKVN + kvh * (4 * Dd);
    float cv = cosb[s * Dd + d], sv = sinb[s * Dd + d];
    __shared__ float buf[Dd];
    __shared__ float red[Dd];
    for (int sub = 0; sub < 3; sub++) {
        float x = base[sub * Dd + d];
        buf[d] = x; __syncthreads();
        float rot = (d < 32) ? -buf[d + 32] : buf[d - 32];
        float y = x * cv + rot * sv;
        red[d] = y * y; __syncthreads();
        for (int o = 32; o > 0; o >>= 1) { if (d < o) red[d] += red[d + o]; __syncthreads(); }
        float inv = rsqrtf(red[0] / Dd + 1e-6f);
        float outv = y * inv * (sub < 2 ? qw[d] : kw[d]);
        if (sub < 2) g_q[((size_t)(kvh*2 + sub) * SS + s) * Dd + d] = outv;
        else         g_k[((size_t)kvh * SS + s) * Dd + d] = outv;
        __syncthreads();
    }
    g_vT[((size_t)kvh * Dd + d) * SS + s] = base[3 * Dd + d];
}

// ---------------- causal softmax; zero-fill only the PV-read window ----------------
__global__ void softmax_causal_k()
{
    int q = blockIdx.x, h = blockIdx.y;
    float* row = g_scores + ((size_t)h * SS + q) * SS;
    int n = q + 1;
    int lim = ((q >> 7) + 1) << 7;
    __shared__ float red[256];
    float m = -1e30f;
    for (int i = threadIdx.x; i < n; i += 256) m = fmaxf(m, row[i]);
    red[threadIdx.x] = m; __syncthreads();
    for (int o = 128; o > 0; o >>= 1) { if (threadIdx.x < o) red[threadIdx.x] = fmaxf(red[threadIdx.x], red[threadIdx.x + o]); __syncthreads(); }
    m = red[0]; __syncthreads();
    float sum = 0.f;
    for (int i = threadIdx.x; i < n; i += 256) { float e = expf(row[i] - m); row[i] = e; sum += e; }
    red[threadIdx.x] = sum; __syncthreads();
    for (int o = 128; o > 0; o >>= 1) { if (threadIdx.x < o) red[threadIdx.x] += red[threadIdx.x + o]; __syncthreads(); }
    float inv = 1.f / red[0];
    for (int i = threadIdx.x; i < n; i += 256) row[i] *= inv;
    for (int i = n + threadIdx.x; i < lim; i += 256) row[i] = 0.f;
}

// ---------------- gating: softmax over 64 + top-8 ----------------
__global__ void gate_topk_k()
{
    int s = blockIdx.x, e = threadIdx.x;
    __shared__ float vals[En], red[En];
    float l = g_logits[s * En + e];
    red[e] = l; __syncthreads();
    for (int o = 32; o > 0; o >>= 1) { if (e < o) red[e] = fmaxf(red[e], red[e + o]); __syncthreads(); }
    float mx = red[0]; __syncthreads();
    float g = expf(l - mx);
    red[e] = g; __syncthreads();
    for (int o = 32; o > 0; o >>= 1) { if (e < o) red[e] += red[e + o]; __syncthreads(); }
    float inv = 1.f / red[0]; __syncthreads();
    vals[e] = g * inv; __syncthreads();
    if (e == 0) {
        float tv[Kk]; float sum8 = 0.f; unsigned long long used = 0;
        for (int k = 0; k < Kk; k++) {
            int best = 0; float bv = -1e30f;
            for (int j = 0; j < En; j++)
                if (!((used >> j) & 1ull) && vals[j] > bv) { bv = vals[j]; best = j; }
            used |= 1ull << best;
            g_topi[s * Kk + k] = best; tv[k] = bv; sum8 += bv;
        }
        if (sum8 < F32EPS) sum8 = F32EPS;
        for (int k = 0; k < Kk; k++) g_topw[s * Kk + k] = tv[k] / sum8;
    }
}

// ---------------- deterministic capacity dispatch (warp-parallel, order-preserving) ----------------
__global__ void dispatch_k()
{
    __shared__ int ti[SS * Kk];   // 32 KB
    int tid = threadIdx.x;
    for (int i = tid; i < SS * Kk; i += 1024) ti[i] = g_topi[i];
    __syncthreads();
    int w = tid >> 5, lane = tid & 31;
    unsigned lmask = (1u << lane) - 1u;
    #pragma unroll
    for (int half = 0; half < 2; half++) {
        int e = w + half * 32;
        int cnt = 0;
        for (int k = 0; k < Kk; k++) {
            for (int s0 = 0; s0 < SS; s0 += 32) {
                int s = s0 + lane;
                int match = (ti[s * Kk + k] == e);
                unsigned bal = __ballot_sync(0xFFFFFFFFu, match);
                if (match) {
                    int pos = cnt + __popc(bal & lmask);
                    if (pos < CAPn) { g_etok[e * CAPn + pos] = s; g_slot[s * Kk + k] = pos; }
                    else            g_slot[s * Kk + k] = -1;
                }
                cnt += __popc(bal);
            }
        }
        if (lane == 0) g_ne[e] = cnt < CAPn ? cnt : CAPn;
    }
}

// ---------------- gather tokens per expert, packed bf16 (zero-pad to CAP) ----------------
__global__ void gather_k()
{
    int c = blockIdx.x, e = blockIdx.y;
    uint32_t* dst = g_Xe + ((size_t)e * CAPn + c) * (Hd/2);
    if (c < g_ne[e]) {
        const float* src = g_x2 + (size_t)g_etok[e * CAPn + c] * Hd;
        for (int i = threadIdx.x; i < Hd/2; i += 256)
            dst[i] = pack_bf16(src[2*i], src[2*i + 1]);
    } else {
        for (int i = threadIdx.x; i < Hd/2; i += 256) dst[i] = 0u;
    }
}

// ---------------- final combine ----------------
__global__ void combine_k(float* __restrict__ out)
{
    int s = blockIdx.x, ti = threadIdx.x;
    __shared__ int sl[Kk], ei[Kk];
    __shared__ float wt[Kk];
    if (ti < Kk) { sl[ti] = g_slot[s*Kk+ti]; ei[ti] = g_topi[s*Kk+ti]; wt[ti] = g_topw[s*Kk+ti]; }
    __syncthreads();
    for (int m = ti; m < Hd; m += 256) {
        float acc = g_hidden[(size_t)s * Hd + m] + g_shared[(size_t)s * Hd + m];
        #pragma unroll
        for (int k = 0; k < Kk; k++) {
            int slot = sl[k];
            if (slot >= 0) acc += wt[k] * g_eout[((size_t)ei[k] * CAPn + slot) * Hd + m];
        }
        out[(size_t)s * Hd + m] = acc;
    }
}

// ---------------- host launcher ----------------
extern "C" void kernel_launch(void* const* d_in, const int* in_sizes, int n_in,
                              void* d_out, int out_size)
{
    const float* hs        = (const float*)d_in[0];
    const float* cosb      = (const float*)d_in[1];
    const float* sinb      = (const float*)d_in[2];
    const float* input_lnw = (const float*)d_in[3];
    const float* post_lnw  = (const float*)d_in[4];
    const float* qkv_w     = (const float*)d_in[5];
    const float* o_w       = (const float*)d_in[6];
    const float* q_lnw     = (const float*)d_in[7];
    const float* k_lnw     = (const float*)d_in[8];
    const float* gate_w    = (const float*)d_in[9];
    const float* sgu_w     = (const float*)d_in[10];
    const float* sdown_w   = (const float*)d_in[11];
    const float* egu_w     = (const float*)d_in[12];
    const float* edown_w   = (const float*)d_in[13];
    float* out = (float*)d_out;

    float *p_xnorm, *p_qkv, *p_q, *p_k, *p_vT, *p_scores, *p_attn, *p_hidden,
          *p_x2, *p_act, *p_shared, *p_logits, *p_eout;
    uint32_t *p_Xe, *p_acte, *p_eguw, *p_ednw;
    int* p_ne;
    cudaGetSymbolAddress((void**)&p_xnorm,  g_xnorm);
    cudaGetSymbolAddress((void**)&p_qkv,    g_qkv);
    cudaGetSymbolAddress((void**)&p_q,      g_q);
    cudaGetSymbolAddress((void**)&p_k,      g_k);
    cudaGetSymbolAddress((void**)&p_vT,     g_vT);
    cudaGetSymbolAddress((void**)&p_scores, g_scores);
    cudaGetSymbolAddress((void**)&p_attn,   g_attn);
    cudaGetSymbolAddress((void**)&p_hidden, g_hidden);
    cudaGetSymbolAddress((void**)&p_x2,     g_x2);
    cudaGetSymbolAddress((void**)&p_act,    g_act);
    cudaGetSymbolAddress((void**)&p_shared, g_shared);
    cudaGetSymbolAddress((void**)&p_logits, g_logits);
    cudaGetSymbolAddress((void**)&p_Xe,     g_Xe);
    cudaGetSymbolAddress((void**)&p_acte,   g_acte);
    cudaGetSymbolAddress((void**)&p_eout,   g_eout);
    cudaGetSymbolAddress((void**)&p_eguw,   g_eguw);
    cudaGetSymbolAddress((void**)&p_ednw,   g_ednw);
    cudaGetSymbolAddress((void**)&p_ne,     g_ne);

    static cudaStream_t s2 = nullptr;
    static cudaEvent_t evF = nullptr, evJ = nullptr, evA = nullptr, evD = nullptr;
    if (!s2) {
        cudaStreamCreateWithFlags(&s2, cudaStreamNonBlocking);
        cudaEventCreateWithFlags(&evF, cudaEventDisableTiming);
        cudaEventCreateWithFlags(&evJ, cudaEventDisableTiming);
        cudaEventCreateWithFlags(&evA, cudaEventDisableTiming);
        cudaEventCreateWithFlags(&evD, cudaEventDisableTiming);
    }

    dim3 blk(256);

    // s2: convert expert weights fp32 -> packed bf16 (hidden under attention phase)
    const long long gu_n4 = (long long)En * FFn * Hd / 4;   // uint32 count / 4
    const long long dn_n4 = (long long)En * Hd * FFn / 8;
    cvtw_k<<<(unsigned)(gu_n4 / 256), blk, 0, s2>>>(egu_w, p_eguw, gu_n4);
    cvtw_k<<<(unsigned)(dn_n4 / 256), blk, 0, s2>>>(edown_w, p_ednw, dn_n4);

    // default: 1) input RMSNorm
    rmsnorm_k<<<SS, blk>>>(hs, input_lnw, p_xnorm);
    // 2) QKV GEMM (tf32 mma)
    gemm_mma<<<dim3(QKVN/128, SS/128, 1), blk>>>(p_xnorm, qkv_w, p_qkv, nullptr,
        Hd, Hd, Hd, QKVN, 1.f, 0,1, 0,1, 0,1, nullptr, 0);
    // 3) split + RoPE + q/k RMSNorm + vT
    rope_split_k<<<dim3(SS, KVHn), Dd>>>(cosb, sinb, q_lnw, k_lnw);
    // 4) scores = q @ k^T / 8 (tf32 mma, causal tile skip)
    gemm_mma<<<dim3(SS/128, SS/128, NHq), blk>>>(p_q, p_k, p_scores, nullptr,
        Dd, Dd, Dd, SS, 0.125f,
        (long long)SS*Dd, 1, (long long)SS*Dd, 2, (long long)SS*SS, 1, nullptr, 1);
    // 5) causal softmax (zero-fill truncated to PV window)
    softmax_causal_k<<<dim3(SS, NHq), blk>>>();
    // 6) attn = P @ V (tf32 mma, causal K truncation)
    gemm_pv<<<dim3(1, SS/128, NHq), blk>>>(p_scores, p_vT, p_attn,
        SS, SS, SS, HQn,
        (long long)SS*SS, (long long)Dd*SS, (long long)Dd);
    // 7) O-proj + residual (tf32 mma)
    gemm_mma<<<dim3(Hd/128, SS/128, 1), blk>>>(p_attn, o_w, p_hidden, hs,
        HQn, HQn, HQn, Hd, 1.f, 0,1, 0,1, 0,1, nullptr, 0);
    // 8) post RMSNorm
    rmsnorm_k<<<SS, blk>>>(p_hidden, post_lnw, p_x2);

    // ---- fork (R9 topology): gating chain on s2 (after converts) overlaps shared MLP ----
    cudaEventRecord(evF, 0);
    cudaStreamWaitEvent(s2, evF, 0);

    gemm_nt<<<dim3(En/64, SS/64, 1), blk, 0, s2>>>(p_x2, gate_w, p_logits, nullptr,
        SS, En, Hd, Hd, Hd, En, 1.f, 0,1, 0,1, 0,1, nullptr, 0);
    gate_topk_k<<<SS, En, 0, s2>>>();
    dispatch_k<<<1, 1024, 0, s2>>>();
    gather_k<<<dim3(CAPn, En), blk, 0, s2>>>();
    cudaEventRecord(evJ, s2);

    gemm_guact_tf32<<<dim3(FFn/64, SS/128, 1), blk>>>(p_x2, sgu_w, p_act,
        Hd, Hd, Hd, FFn, FFn);
    gemm_mma<<<dim3(Hd/128, SS/128, 1), blk>>>(p_act, sdown_w, p_shared, nullptr,
        FFn, FFn, FFn, Hd, 1.f, 0,1, 0,1, 0,1, nullptr, 0);

    cudaStreamWaitEvent(0, evJ, 0);
    // ---- join (covers weight converts via s2 ordering) ----

    const long long sXe2 = (long long)CAPn*Hd/2;
    const long long sGu2 = (long long)FFn*Hd;       // uint32 per expert (2*FFn*Hd bf16)
    const long long sAc2 = (long long)CAPn*FFn/2;
    const long long sDn2 = (long long)Hd*FFn/2;     // uint32 per expert
    const long long sEo  = (long long)CAPn*Hd;
    const int EH = En/2;   // 32 experts per half (R12-proven 2-chunk pipeline)

    // expert guact half A (experts 0..31) on default
    gemm_guact_bf16<<<dim3(FFn/64, CAPn/128, EH), blk>>>(p_Xe, p_eguw, p_acte,
        Hd, Hd/2, Hd/2, FFn/2, FFn, sXe2, sGu2, sAc2, p_ne);
    cudaEventRecord(evA, 0);

    // expert guact half B (experts 32..63) on default (overlaps down-A on s2)
    gemm_guact_bf16<<<dim3(FFn/64, CAPn/128, EH), blk>>>(p_Xe + EH*sXe2, p_eguw + EH*sGu2,
        p_acte + EH*sAc2, Hd, Hd/2, Hd/2, FFn/2, FFn, sXe2, sGu2, sAc2, p_ne + EH);

    // s2: down half A after guact-A
    cudaStreamWaitEvent(s2, evA, 0);
    gemm_bf16_ab<<<dim3(Hd/128, CAPn/128, EH), blk, 0, s2>>>(p_acte, p_ednw, p_eout,
        FFn, FFn/2, FFn/2, Hd, sAc2, sDn2, sEo, p_ne);
    cudaEventRecord(evD, s2);

    // default: down half B
    gemm_bf16_ab<<<dim3(Hd/128, CAPn/128, EH), blk>>>(p_acte + EH*sAc2, p_ednw + EH*sDn2,
        p_eout + EH*sEo, FFn, FFn/2, FFn/2, Hd, sAc2, sDn2, sEo, p_ne + EH);

    cudaStreamWaitEvent(0, evD, 0);
    // combine -> output
    combine_k<<<SS, blk>>>(out);
}